// round 8
// baseline (speedup 1.0000x reference)
#include <cuda_runtime.h>
#include <cuda_bf16.h>

#define EPS 1e-6f
#define ITERS 20

__device__ __forceinline__ float frcp(float x) {
    float y;
    asm("rcp.approx.ftz.f32 %0, %1;" : "=f"(y) : "f"(x));
    return y;
}

__global__ __launch_bounds__(256)
void hc_sinkhorn_kernel(const float* __restrict__ mixes,
                        const float* __restrict__ hc_scale,
                        const float* __restrict__ hc_base,
                        float* __restrict__ out,
                        int n_tok)
{
    __shared__ float sb[24];
    __shared__ float ss[3];
    if (threadIdx.x < 24) sb[threadIdx.x] = hc_base[threadIdx.x];
    if (threadIdx.x < 3)  ss[threadIdx.x] = hc_scale[threadIdx.x];
    __syncthreads();

    const int t = blockIdx.x * blockDim.x + threadIdx.x;
    if (t >= n_tok) return;

    const float4* mp = (const float4*)(mixes + (size_t)t * 24);
    float4 v0 = __ldcs(mp + 0);
    float4 v1 = __ldcs(mp + 1);
    float4 v2 = __ldcs(mp + 2);
    float4 v3 = __ldcs(mp + 3);
    float4 v4 = __ldcs(mp + 4);
    float4 v5 = __ldcs(mp + 5);

    const float s0 = ss[0], s1 = ss[1], s2 = ss[2];

    // ---- pre: sigmoid(x*s0 + b) + EPS ----
    float pre[4] = {v0.x, v0.y, v0.z, v0.w};
    #pragma unroll
    for (int i = 0; i < 4; i++)
        pre[i] = frcp(1.0f + __expf(-fmaf(pre[i], s0, sb[i]))) + EPS;

    // ---- post: 2*sigmoid(x*s1 + b) ----
    float post[4] = {v1.x, v1.y, v1.z, v1.w};
    #pragma unroll
    for (int i = 0; i < 4; i++)
        post[i] = 2.0f * frcp(1.0f + __expf(-fmaf(post[i], s1, sb[4 + i])));

    // ---- comb: softmax(rows) + EPS ----
    float m[4][4] = {
        {v2.x, v2.y, v2.z, v2.w},
        {v3.x, v3.y, v3.z, v3.w},
        {v4.x, v4.y, v4.z, v4.w},
        {v5.x, v5.y, v5.z, v5.w},
    };
    #pragma unroll
    for (int i = 0; i < 4; i++) {
        #pragma unroll
        for (int j = 0; j < 4; j++)
            m[i][j] = __expf(fmaf(m[i][j], s2, sb[8 + i * 4 + j]));
        float rs  = (m[i][0] + m[i][1]) + (m[i][2] + m[i][3]);
        float inv = frcp(rs);
        #pragma unroll
        for (int j = 0; j < 4; j++)
            m[i][j] = fmaf(m[i][j], inv, EPS);  // softmax + EPS
    }

    // ---- Sinkhorn via diagonal scaling vectors r, c ----
    // Scaled matrix N_ij = m_ij * r_i * c_j.
    // Col pass:  colsum_j = c_j * S_j,  S_j = sum_i m_ij r_i
    //            c_j <- c_j * rcp(c_j*S_j + EPS)   (exact /(sum+EPS))
    // Row pass:  symmetric with T_i = sum_j m_ij c_j.
    float r[4] = {1.f, 1.f, 1.f, 1.f};
    float c[4];

    // First col-normalize (r = c = 1): c_j = rcp(S_j + EPS)
    #pragma unroll
    for (int j = 0; j < 4; j++) {
        float S = (m[0][j] + m[1][j]) + (m[2][j] + m[3][j]);
        c[j] = frcp(S + EPS);
    }

    #pragma unroll 1
    for (int it = 0; it < ITERS - 1; it++) {
        // Row normalize
        #pragma unroll
        for (int i = 0; i < 4; i++) {
            float T = fmaf(m[i][0], c[0],
                      fmaf(m[i][1], c[1],
                      fmaf(m[i][2], c[2], m[i][3] * c[3])));
            r[i] = r[i] * frcp(fmaf(r[i], T, EPS));
        }
        // Col normalize
        #pragma unroll
        for (int j = 0; j < 4; j++) {
            float S = fmaf(m[0][j], r[0],
                      fmaf(m[1][j], r[1],
                      fmaf(m[2][j], r[2], m[3][j] * r[3])));
            c[j] = c[j] * frcp(fmaf(c[j], S, EPS));
        }
    }

    // ---- Outputs: [pre | post | comb], each token-major ----
    float4* op = (float4*)out;
    float4* oq = (float4*)(out + (size_t)n_tok * 4);
    float4* oc = (float4*)(out + (size_t)n_tok * 8);

    __stcs(op + t, make_float4(pre[0], pre[1], pre[2], pre[3]));
    __stcs(oq + t, make_float4(post[0], post[1], post[2], post[3]));

    #pragma unroll
    for (int i = 0; i < 4; i++) {
        float ri = r[i];
        __stcs(oc + (size_t)t * 4 + i,
               make_float4(m[i][0] * c[0] * ri,
                           m[i][1] * c[1] * ri,
                           m[i][2] * c[2] * ri,
                           m[i][3] * c[3] * ri));
    }
}

extern "C" void kernel_launch(void* const* d_in, const int* in_sizes, int n_in,
                              void* d_out, int out_size)
{
    const float* mixes    = (const float*)d_in[0];
    const float* hc_scale = (const float*)d_in[1];
    const float* hc_base  = (const float*)d_in[2];
    // d_in[3] = hc_mult (4), d_in[4] = sinkhorn_iters (20): fixed by problem setup.

    const int n_tok = in_sizes[0] / 24;   // 24 features per token
    const int block = 256;
    const int grid  = (n_tok + block - 1) / block;

    hc_sinkhorn_kernel<<<grid, block>>>(mixes, hc_scale, hc_base, (float*)d_out, n_tok);
}